// round 3
// baseline (speedup 1.0000x reference)
#include <cuda_runtime.h>
#include <cstdint>

// Problem constants
#define B_   8
#define H_   224
#define HW_  (H_*H_)          // 50176
#define OC_  32
#define NH_  8
#define HD_  4
#define NPIX (B_*HW_)         // 401408
#define X1_N (B_*OC_*HW_)     // 12845056
#define QKV_N (B_*96*HW_)     // 38535168
#define ATT_N (B_*NH_*HD_*H_*H_) // 12845056

// Scratch (static device globals; no allocation allowed)
__device__ float g_x1[X1_N];
__device__ float g_qkv[QKV_N];
__device__ float g_A2[X1_N];
__device__ int   g_jidx[B_*NH_*HD_*H_];   // 57344
__device__ float g_wc[32*32];
__device__ float g_bc[32];
__device__ float g_sum[32];
__device__ float g_sq[32];

// ---------------------------------------------------------------- prep
__global__ void k_prep(const float* __restrict__ upd_w, const float* __restrict__ proj_w,
                       const float* __restrict__ proj_b, const float* __restrict__ upd_b) {
    int t = threadIdx.x;            // 1024 threads
    int o = t >> 5, c = t & 31;
    float s = 0.f;
    #pragma unroll
    for (int m = 0; m < 32; m++) s += upd_w[o*32+m] * proj_w[m*32+c];
    g_wc[o*32+c] = s;
    if (c == 0) {
        float bsum = upd_b[o];
        #pragma unroll
        for (int m = 0; m < 32; m++) bsum += upd_w[o*32+m] * proj_b[m];
        g_bc[o] = bsum;
    }
    if (t < 32) { g_sum[t] = 0.f; g_sq[t] = 0.f; }
}

// ---------------------------------------------------------------- zero att
__global__ void k_zero(float4* __restrict__ p) {
    int i = blockIdx.x * 256 + threadIdx.x;   // grid covers ATT_N/4 exactly
    p[i] = make_float4(0.f, 0.f, 0.f, 0.f);
}

// ---------------------------------------------------------------- conv_in: 3->32, 3x3, pad 1
__global__ __launch_bounds__(256) void k_conv_in(const float* __restrict__ x,
                                                 const float* __restrict__ w,
                                                 const float* __restrict__ bias) {
    __shared__ float ws[32*27];
    __shared__ float bs[32];
    int t = threadIdx.x;
    for (int i = t; i < 864; i += 256) ws[i] = w[i];
    if (t < 32) bs[t] = bias[t];
    __syncthreads();
    int pix = blockIdx.x * 256 + t;           // < NPIX exact
    int b = pix / HW_; int hw = pix % HW_;
    int h = hw / H_, wd = hw % H_;
    float acc[32];
    #pragma unroll
    for (int o = 0; o < 32; o++) acc[o] = bs[o];
    for (int c = 0; c < 3; c++) {
        #pragma unroll
        for (int kr = 0; kr < 3; kr++) {
            int ih = h + kr - 1; if (ih < 0 || ih >= H_) continue;
            #pragma unroll
            for (int kc = 0; kc < 3; kc++) {
                int iw = wd + kc - 1; if (iw < 0 || iw >= H_) continue;
                float xv = x[((b*3 + c)*H_ + ih)*H_ + iw];
                int wi = c*9 + kr*3 + kc;
                #pragma unroll
                for (int o = 0; o < 32; o++) acc[o] += xv * ws[o*27 + wi];
            }
        }
    }
    #pragma unroll
    for (int o = 0; o < 32; o++) g_x1[((b*32 + o)*H_ + h)*H_ + wd] = acc[o];
}

// ---------------------------------------------------------------- conv_qkv: 32->96, 3x3, pad 1
// block: 256 thr, 32x32 pixel tile, thread = (row, 4-col group), 8 oc per block (grid.y)
__global__ __launch_bounds__(256) void k_conv_qkv(const float* __restrict__ w) {
    __shared__ float ps[8][34][36];
    __shared__ float wsm[8][8][9];
    int t = threadIdx.x;
    int tile = blockIdx.x;                 // 0..391
    int b = tile / 49; int th = (tile % 49) / 7, tw = tile % 7;
    int h0 = th * 32, w0 = tw * 32;
    int oc0 = blockIdx.y * 8;              // 0..11
    int r = t >> 3, cg = t & 7;
    float acc[32];
    #pragma unroll
    for (int i = 0; i < 32; i++) acc[i] = 0.f;
    for (int g = 0; g < 4; g++) {
        __syncthreads();
        for (int i = t; i < 8*34*34; i += 256) {
            int ic = i / (34*34); int rr = (i / 34) % 34; int cc = i % 34;
            int ih = h0 + rr - 1, iw = w0 + cc - 1;
            float v = 0.f;
            if (ih >= 0 && ih < H_ && iw >= 0 && iw < H_)
                v = g_x1[((b*32 + g*8 + ic)*H_ + ih)*H_ + iw];
            ps[ic][rr][cc] = v;
        }
        for (int i = t; i < 8*8*9; i += 256) {
            int oc = i / 72; int rem = i % 72; int ic = rem / 9; int tap = rem % 9;
            wsm[oc][ic][tap] = w[((oc0 + oc)*32 + g*8 + ic)*9 + tap];
        }
        __syncthreads();
        #pragma unroll
        for (int ic = 0; ic < 8; ic++) {
            #pragma unroll
            for (int kr = 0; kr < 3; kr++) {
                #pragma unroll
                for (int kc = 0; kc < 3; kc++) {
                    float wv[8], pv[4];
                    #pragma unroll
                    for (int o = 0; o < 8; o++) wv[o] = wsm[o][ic][kr*3 + kc];
                    #pragma unroll
                    for (int p = 0; p < 4; p++) pv[p] = ps[ic][r + kr][cg*4 + p + kc];
                    #pragma unroll
                    for (int o = 0; o < 8; o++)
                        #pragma unroll
                        for (int p = 0; p < 4; p++) acc[o*4 + p] += wv[o] * pv[p];
                }
            }
        }
    }
    int hh = h0 + r;
    #pragma unroll
    for (int o = 0; o < 8; o++)
        #pragma unroll
        for (int p = 0; p < 4; p++)
            g_qkv[((b*96 + oc0 + o)*H_ + hh)*H_ + w0 + cg*4 + p] = acc[o*4 + p];
}

// ---------------------------------------------------------------- attention argmax + one-hot
// block = (bnd, i-tile of 16); 128 threads (4 warps); warp handles 4 i rows, lane = j within tile
__global__ __launch_bounds__(128) void k_att(const float* __restrict__ gumbel,
                                             float* __restrict__ att) {
    __shared__ float Qs[16][228];
    __shared__ float Ks[32][228];
    int bnd = blockIdx.x;                 // 0..255 = b*32 + n*4 + d
    int it = blockIdx.y;                  // 0..13
    int b = bnd >> 5; int nd = bnd & 31; int n = nd >> 2; int d = nd & 3;
    const float* qbase = g_qkv + (size_t)(b*96 + n*12 + d) * HW_;
    const float* kbase = g_qkv + (size_t)(b*96 + n*12 + 4 + d) * HW_;
    int t = threadIdx.x; int lane = t & 31; int wid = t >> 5;
    int i0 = it * 16;
    for (int i = t; i < 16*H_; i += 128) {
        int rr = i / H_, cc = i % H_;
        Qs[rr][cc] = qbase[(i0 + rr)*H_ + cc];
    }
    float best[4]; int bj[4];
    #pragma unroll
    for (int r = 0; r < 4; r++) { best[r] = -1e30f; bj[r] = 0; }

    for (int jt = 0; jt < H_; jt += 32) {
        __syncthreads();
        for (int i = t; i < 32*H_; i += 128) {
            int rr = i / H_, cc = i % H_;
            Ks[rr][cc] = kbase[(jt + rr)*H_ + cc];
        }
        __syncthreads();
        float acc[4] = {0.f, 0.f, 0.f, 0.f};
        for (int w = 0; w < H_; w += 4) {
            float4 kv = *(const float4*)&Ks[lane][w];
            #pragma unroll
            for (int r = 0; r < 4; r++) {
                float4 qv = *(const float4*)&Qs[wid*4 + r][w];
                acc[r] += kv.x*qv.x + kv.y*qv.y + kv.z*qv.z + kv.w*qv.w;
            }
        }
        int j = jt + lane;
        #pragma unroll
        for (int r = 0; r < 4; r++) {
            int i = i0 + wid*4 + r;
            float v = acc[r]*0.5f + gumbel[((size_t)bnd*H_ + i)*H_ + j];
            if (v > best[r]) { best[r] = v; bj[r] = j; }
        }
    }
    #pragma unroll
    for (int r = 0; r < 4; r++) {
        float v = best[r]; int j = bj[r];
        #pragma unroll
        for (int off = 16; off; off >>= 1) {
            float v2 = __shfl_down_sync(0xffffffffu, v, off);
            int   j2 = __shfl_down_sync(0xffffffffu, j, off);
            if (v2 > v || (v2 == v && j2 < j)) { v = v2; j = j2; }
        }
        if (lane == 0) {
            int i = i0 + wid*4 + r;
            g_jidx[bnd*H_ + i] = j;
            att[((size_t)bnd*H_ + i)*H_ + j] = 1.0f;
        }
    }
}

// ---------------------------------------------------------------- gather v rows + fused 1x1 convs + BN partial sums
// block per (b, i); 224 threads (one per w)
__global__ __launch_bounds__(224) void k_gather_proj() {
    __shared__ float wcs[1024];
    __shared__ float bcs[32];
    __shared__ int   js[32];
    __shared__ float rs[32][7];
    __shared__ float rq[32][7];
    int b = blockIdx.x / H_; int i = blockIdx.x % H_;
    int t = threadIdx.x;
    for (int k = t; k < 1024; k += 224) wcs[k] = g_wc[k];
    if (t < 32) {
        bcs[t] = g_bc[t];
        js[t] = g_jidx[(b*32 + t)*H_ + i];   // t = n*4+d
    }
    __syncthreads();
    float a[32];
    #pragma unroll
    for (int c = 0; c < 32; c++) {
        int n = c >> 2, d = c & 3;
        a[c] = g_qkv[((size_t)(b*96 + n*12 + 8 + d)*H_ + js[c])*H_ + t];
    }
    float out[32];
    #pragma unroll
    for (int o = 0; o < 32; o++) {
        float s = bcs[o];
        #pragma unroll
        for (int c = 0; c < 32; c++) s += wcs[o*32 + c] * a[c];
        out[o] = s;
        g_A2[((size_t)(b*32 + o)*H_ + i)*H_ + t] = s;
    }
    int wid = t >> 5, lane = t & 31;
    #pragma unroll
    for (int o = 0; o < 32; o++) {
        float s = out[o], q = out[o]*out[o];
        #pragma unroll
        for (int off = 16; off; off >>= 1) {
            s += __shfl_down_sync(0xffffffffu, s, off);
            q += __shfl_down_sync(0xffffffffu, q, off);
        }
        if (lane == 0) { rs[o][wid] = s; rq[o][wid] = q; }
    }
    __syncthreads();
    if (t < 32) {
        float s = 0.f, q = 0.f;
        #pragma unroll
        for (int k = 0; k < 7; k++) { s += rs[t][k]; q += rq[t][k]; }
        atomicAdd(&g_sum[t], s);
        atomicAdd(&g_sq[t], q);
    }
}

// ---------------------------------------------------------------- BN + SiLU + residual
__global__ __launch_bounds__(256) void k_final(const float* __restrict__ gamma,
                                               const float* __restrict__ beta,
                                               float* __restrict__ outp) {
    int idx = blockIdx.x * 256 + threadIdx.x;   // < X1_N exact
    int c = (idx / HW_) & 31;
    const float inv_n = 1.f / (float)NPIX;
    float mean = g_sum[c] * inv_n;
    float var = g_sq[c] * inv_n - mean*mean;
    float v = (g_A2[idx] - mean) * rsqrtf(var + 1e-5f) * gamma[c] + beta[c];
    v = v / (1.f + expf(-v));
    outp[idx] = v + g_x1[idx];
}

// ---------------------------------------------------------------- launch
extern "C" void kernel_launch(void* const* d_in, const int* in_sizes, int n_in,
                              void* d_out, int out_size) {
    const float* x      = (const float*)d_in[0];
    const float* gumbel = (const float*)d_in[1];
    const float* in_w   = (const float*)d_in[2];
    const float* in_b   = (const float*)d_in[3];
    const float* qkv_w  = (const float*)d_in[4];
    const float* proj_w = (const float*)d_in[5];
    const float* proj_b = (const float*)d_in[6];
    const float* upd_w  = (const float*)d_in[7];
    const float* upd_b  = (const float*)d_in[8];
    const float* bn_g   = (const float*)d_in[9];
    const float* bn_b   = (const float*)d_in[10];
    float* outp = (float*)d_out;
    float* att  = outp + X1_N;                 // (out, att) concatenated

    k_prep<<<1, 1024>>>(upd_w, proj_w, proj_b, upd_b);
    k_zero<<<ATT_N/4/256, 256>>>((float4*)att);
    k_conv_in<<<NPIX/256, 256>>>(x, in_w, in_b);
    k_conv_qkv<<<dim3(392, 12), 256>>>(qkv_w);
    k_att<<<dim3(256, 14), 128>>>(gumbel, att);
    k_gather_proj<<<B_*H_, 224>>>();
    k_final<<<X1_N/256, 256>>>(bn_g, bn_b, outp);
}